// round 4
// baseline (speedup 1.0000x reference)
#include <cuda_runtime.h>
#include <cstdint>

#define N_NODES 100000
#define HIDDEN  128
#define NPB     128   // nodes per block in GEMM kernel
#define CAP     48    // per-node edge bin capacity (Poisson mean 16; P(>=48)~1e-10)

// Scratch (device globals — allocation-free rule).
// INVARIANT: g_cnt[] and g_ovf_cnt are ZERO at kernel_launch entry.
// (zero-initialized at module load; re-zeroed at the end of each call by k_fix)
__device__ __align__(16) float g_S  [(size_t)N_NODES * HIDDEN];
__device__ __align__(16) float g_I  [(size_t)N_NODES * HIDDEN];
__device__ int   g_cnt[N_NODES];
__device__ int   g_bin[(size_t)N_NODES * CAP];
__device__ int   g_ovf_cnt;
__device__ int   g_ovf[2 * 1600000];

// Packed fp32x2 FMA (Blackwell): 2x FFMA throughput vs scalar FFMA
__device__ __forceinline__ unsigned long long ffma2(unsigned long long a,
                                                    unsigned long long b,
                                                    unsigned long long c) {
    unsigned long long d;
    asm("fma.rn.f32x2 %0, %1, %2, %3;" : "=l"(d) : "l"(a), "l"(b), "l"(c));
    return d;
}
__device__ __forceinline__ unsigned long long dup2(float w) {
    unsigned long long d;
    const unsigned wu = __float_as_uint(w);
    asm("mov.b64 %0, {%1,%1};" : "=l"(d) : "r"(wu));
    return d;
}
__device__ __forceinline__ float sigmoidf(float v) {
    return 1.f / (1.f + __expf(-v));
}

// ---------------------------------------------------------------------------
// K1: sigmoid GEMM for s in {0,1}. Register tile: 4 outputs x 16 nodes/thread.
// Fuses: out[2] = gamma*I, out[3] = 0, and EDGE BINNING (grid-stride tail —
// independent of GEMM results, overlaps with other blocks' compute waves).
// ---------------------------------------------------------------------------
__global__ __launch_bounds__(256, 1) void k_gemm(
    const float* __restrict__ x, const float* __restrict__ W,
    const float* __restrict__ b, float* __restrict__ out,
    const int* __restrict__ rows, const int* __restrict__ cols, int n_edges)
{
    extern __shared__ float sh[];
    float* Ws   = sh;                     // 128 x 132 (pitch 132)
    float* xs   = sh + 128 * 132;         // 128 x 130 (pitch 130)
    float* sgam = xs + 128 * 130;         // 128

    const int tid   = threadIdx.x;
    const int o_grp = tid & 31;
    const int o0    = o_grp * 4;
    const int n_grp = tid >> 5;
    const int n0    = n_grp * 16;
    const int base  = blockIdx.x * NPB;
    const int nn    = min(NPB, N_NODES - base);

    // Ws[h*132 + o] = W[o*128 + h]
    for (int idx = tid; idx < HIDDEN * HIDDEN; idx += 256) {
        Ws[(idx & 127) * 132 + (idx >> 7)] = W[idx];
    }
    // gamma = x[3, node, 1]
    if (tid < NPB) {
        sgam[tid] = (tid < nn)
            ? x[((size_t)3 * N_NODES + base + tid) * HIDDEN + 1] : 0.f;
    }

    float bias[4];
    #pragma unroll
    for (int oi = 0; oi < 4; ++oi) bias[oi] = b[o0 + oi];
    __syncthreads();

    for (int s = 0; s < 2; ++s) {
        // xs[h*130 + n] = x[s, base+n, h]
        const float* xsrc = x + ((size_t)s * N_NODES + base) * HIDDEN;
        for (int idx = tid; idx < NPB * HIDDEN; idx += 256) {
            const int n = idx >> 7, h = idx & 127;
            xs[h * 130 + n] = (n < nn) ? xsrc[idx] : 0.f;
        }
        __syncthreads();

        unsigned long long acc[4][8];
        #pragma unroll
        for (int oi = 0; oi < 4; ++oi)
            #pragma unroll
            for (int p = 0; p < 8; ++p) acc[oi][p] = 0ull;

        #pragma unroll 2
        for (int h = 0; h < HIDDEN; ++h) {
            const float4 w4 = *reinterpret_cast<const float4*>(&Ws[h * 132 + o0]);
            unsigned long long w2[4];
            w2[0] = dup2(w4.x); w2[1] = dup2(w4.y);
            w2[2] = dup2(w4.z); w2[3] = dup2(w4.w);
            const float* xr = &xs[h * 130 + n0];
            #pragma unroll
            for (int p = 0; p < 8; ++p) {
                const unsigned long long xv =
                    *reinterpret_cast<const unsigned long long*>(xr + 2 * p);
                #pragma unroll
                for (int oi = 0; oi < 4; ++oi)
                    acc[oi][p] = ffma2(xv, w2[oi], acc[oi][p]);
            }
        }

        // Epilogue
        #pragma unroll
        for (int p = 0; p < 8; ++p) {
            float lo[4], hi[4];
            #pragma unroll
            for (int oi = 0; oi < 4; ++oi) {
                lo[oi] = sigmoidf(__uint_as_float((unsigned)(acc[oi][p] & 0xffffffffull)) + bias[oi]);
                hi[oi] = sigmoidf(__uint_as_float((unsigned)(acc[oi][p] >> 32)) + bias[oi]);
            }
            const int nA = n0 + 2 * p, nB = nA + 1;
            #pragma unroll
            for (int half = 0; half < 2; ++half) {
                const int n = half ? nB : nA;
                if (n >= nn) continue;
                const float* v = half ? hi : lo;
                const float4 v4 = make_float4(v[0], v[1], v[2], v[3]);
                const size_t off = ((size_t)(base + n)) * HIDDEN + o0;
                if (s == 0) {
                    *reinterpret_cast<float4*>(g_S + off) = v4;
                } else {
                    *reinterpret_cast<float4*>(g_I + off) = v4;
                    const float gm = sgam[n];
                    *reinterpret_cast<float4*>(out + (size_t)2 * N_NODES * HIDDEN + off)
                        = make_float4(gm * v4.x, gm * v4.y, gm * v4.z, gm * v4.w);
                    *reinterpret_cast<float4*>(out + (size_t)3 * N_NODES * HIDDEN + off)
                        = make_float4(0.f, 0.f, 0.f, 0.f);
                }
            }
        }
        __syncthreads();
    }

    // Edge binning tail (overlaps with other blocks' compute).
    // g_cnt was zeroed by the previous call's k_fix (or static init).
    const int stride = gridDim.x * 256;
    for (int e = blockIdx.x * 256 + tid; e < n_edges; e += stride) {
        int r = rows[e], c = cols[e];
        r = min(max(r, 0), N_NODES - 1);
        c = min(max(c, 0), N_NODES - 1);
        const int slot = atomicAdd(&g_cnt[r], 1);
        if (slot < CAP) {
            g_bin[(size_t)r * CAP + slot] = c;
        } else {
            const int o = atomicAdd(&g_ovf_cnt, 1);
            g_ovf[2 * o] = r;
            g_ovf[2 * o + 1] = c;
        }
    }
}

// ---------------------------------------------------------------------------
// K2: gather + finalize. Warp per node, MLP=8: AI = sum_{in-edges} I[col],
//     dS = -beta*AI*S ; dI = -dS - gamma*I. No float atomics.
// ---------------------------------------------------------------------------
__global__ __launch_bounds__(256) void k_gather_final(
    const float* __restrict__ x, float* __restrict__ out)
{
    const int node = (blockIdx.x * 256 + threadIdx.x) >> 5;
    if (node >= N_NODES) return;
    const int lane = threadIdx.x & 31;

    const int d = min(g_cnt[node], CAP);
    const int* __restrict__ bin = g_bin + (size_t)node * CAP;
    const float4* __restrict__ I4 = reinterpret_cast<const float4*>(g_I);

    float4 a = make_float4(0.f, 0.f, 0.f, 0.f);
    int i = 0;
    for (; i + 8 <= d; i += 8) {      // 8 outstanding 512B L2 loads per warp
        int c[8];
        #pragma unroll
        for (int k = 0; k < 8; ++k) c[k] = __ldg(&bin[i + k]);
        float4 v[8];
        #pragma unroll
        for (int k = 0; k < 8; ++k) v[k] = I4[(size_t)c[k] * 32 + lane];
        #pragma unroll
        for (int k = 0; k < 8; ++k) {
            a.x += v[k].x; a.y += v[k].y; a.z += v[k].z; a.w += v[k].w;
        }
    }
    if (i + 4 <= d) {
        int c[4];
        #pragma unroll
        for (int k = 0; k < 4; ++k) c[k] = __ldg(&bin[i + k]);
        float4 v[4];
        #pragma unroll
        for (int k = 0; k < 4; ++k) v[k] = I4[(size_t)c[k] * 32 + lane];
        #pragma unroll
        for (int k = 0; k < 4; ++k) {
            a.x += v[k].x; a.y += v[k].y; a.z += v[k].z; a.w += v[k].w;
        }
        i += 4;
    }
    for (; i < d; ++i) {
        const float4 v = I4[(size_t)__ldg(&bin[i]) * 32 + lane];
        a.x += v.x; a.y += v.y; a.z += v.z; a.w += v.w;
    }

    const float beta = x[((size_t)3 * N_NODES + node) * HIDDEN];
    const size_t fo = (size_t)node * 32 + lane;
    const float4 S4 = reinterpret_cast<const float4*>(g_S)[fo];
    const float4 G4 = reinterpret_cast<const float4*>(
        out + (size_t)2 * N_NODES * HIDDEN)[fo];

    float4 dS, dI;
    dS.x = -beta * a.x * S4.x;  dI.x = -dS.x - G4.x;
    dS.y = -beta * a.y * S4.y;  dI.y = -dS.y - G4.y;
    dS.z = -beta * a.z * S4.z;  dI.z = -dS.z - G4.z;
    dS.w = -beta * a.w * S4.w;  dI.w = -dS.w - G4.w;

    reinterpret_cast<float4*>(out)[fo] = dS;
    reinterpret_cast<float4*>(out + (size_t)N_NODES * HIDDEN)[fo] = dI;
}

// ---------------------------------------------------------------------------
// K3: overflow fix-up (block 0, expected empty) + re-zero g_cnt/g_ovf_cnt
//     so the NEXT call (graph replay) starts clean.
// ---------------------------------------------------------------------------
__global__ __launch_bounds__(256) void k_fix(
    const float* __restrict__ x, float* __restrict__ out)
{
    if (blockIdx.x == 0) {
        const int n = g_ovf_cnt;
        if (n > 0) {
            const long long total = (long long)n * HIDDEN;
            for (long long idx = threadIdx.x; idx < total; idx += 256) {
                const int e = (int)(idx >> 7);
                const int j = (int)(idx & 127);
                const int r = g_ovf[2 * e];
                const int c = g_ovf[2 * e + 1];
                const float v = g_I[(size_t)c * HIDDEN + j];
                const float beta = x[((size_t)3 * N_NODES + r) * HIDDEN];
                const float delta = -beta * v * g_S[(size_t)r * HIDDEN + j];
                atomicAdd(&out[(size_t)r * HIDDEN + j], delta);
                atomicAdd(&out[(size_t)N_NODES * HIDDEN + (size_t)r * HIDDEN + j], -delta);
            }
        }
        __syncthreads();
        if (threadIdx.x == 0) g_ovf_cnt = 0;
    }
    // All blocks: re-zero g_cnt for the next call.
    for (int i = blockIdx.x * 256 + threadIdx.x; i < N_NODES;
         i += gridDim.x * 256) {
        g_cnt[i] = 0;
    }
}

// ---------------------------------------------------------------------------
extern "C" void kernel_launch(void* const* d_in, const int* in_sizes, int n_in,
                              void* d_out, int out_size)
{
    const float* x    = (const float*)d_in[0];
    const float* W    = (const float*)d_in[1];
    const float* b    = (const float*)d_in[2];
    const int*   rows = (const int*)d_in[3];
    const int*   cols = (const int*)d_in[4];
    float*       out  = (float*)d_out;

    const int n_edges = in_sizes[3];

    const size_t smem = (size_t)(128 * 132 + 128 * 130 + 128) * sizeof(float);
    cudaFuncSetAttribute(k_gemm, cudaFuncAttributeMaxDynamicSharedMemorySize,
                         (int)smem);

    const int gemm_blocks = (N_NODES + NPB - 1) / NPB;
    k_gemm<<<gemm_blocks, 256, smem>>>(x, W, b, out, rows, cols, n_edges);

    const int gf_blocks = (N_NODES * 32 + 255) / 256;  // warp per node
    k_gather_final<<<gf_blocks, 256>>>(x, out);

    k_fix<<<128, 256>>>(x, out);
}

// round 6
// speedup vs baseline: 1.2664x; 1.2664x over previous
#include <cuda_runtime.h>
#include <cstdint>

#define N_NODES 100000
#define HIDDEN  128
#define NPB     128   // nodes per block in GEMM kernel
#define CAP     48    // per-node edge bin capacity (Poisson mean 16; P(>=48)~1e-10)

// Scratch (device globals — allocation-free rule).
// INVARIANT: g_cnt[] and g_ovf_cnt are ZERO at kernel_launch entry
// (zero-init at module load; re-zeroed at the end of every call by k_fix).
__device__ __align__(16) float g_S  [(size_t)N_NODES * HIDDEN];
__device__ __align__(16) float g_I  [(size_t)N_NODES * HIDDEN];
__device__ int   g_cnt[N_NODES];
__device__ int   g_bin[(size_t)N_NODES * CAP];
__device__ int   g_ovf_cnt;
__device__ int   g_ovf[2 * 1600000];

// Packed fp32x2 FMA (Blackwell): 2x FFMA throughput vs scalar FFMA
__device__ __forceinline__ unsigned long long ffma2(unsigned long long a,
                                                    unsigned long long b,
                                                    unsigned long long c) {
    unsigned long long d;
    asm("fma.rn.f32x2 %0, %1, %2, %3;" : "=l"(d) : "l"(a), "l"(b), "l"(c));
    return d;
}
__device__ __forceinline__ unsigned long long dup2(float w) {
    unsigned long long d;
    const unsigned wu = __float_as_uint(w);
    asm("mov.b64 %0, {%1,%1};" : "=l"(d) : "r"(wu));
    return d;
}
__device__ __forceinline__ float sigmoidf(float v) {
    return 1.f / (1.f + __expf(-v));
}

// ---------------------------------------------------------------------------
// K1: sigmoid GEMM for s in {0,1}. 512 threads (16 warps -> 4/SMSP for
// latency hiding). Register tile: 2 outputs x 16 nodes per thread.
//   o_grp = tid&63  -> o0 = 2*o_grp  (LDS.64 of Ws pair, conflict-free)
//   n_grp = tid>>6  -> 16 nodes = 8 pairs (broadcast LDS.64 from xs; n_grp
//                      is warp-uniform, so all xs reads are broadcasts)
// Fuses: out[2] = gamma*I, out[3] = 0.
// ---------------------------------------------------------------------------
__global__ __launch_bounds__(512, 1) void k_gemm(
    const float* __restrict__ x, const float* __restrict__ W,
    const float* __restrict__ b, float* __restrict__ out)
{
    extern __shared__ float sh[];
    float* Ws   = sh;                     // 128 x 132 (pitch 132)
    float* xs   = sh + 128 * 132;         // 128 x 130 (pitch 130, even -> LDS.64 aligned)
    float* sgam = xs + 128 * 130;         // 128

    const int tid   = threadIdx.x;
    const int o0    = (tid & 63) * 2;
    const int n0    = (tid >> 6) * 16;
    const int base  = blockIdx.x * NPB;
    const int nn    = min(NPB, N_NODES - base);

    // Ws[h*132 + o] = W[o*128 + h]
    for (int idx = tid; idx < HIDDEN * HIDDEN; idx += 512) {
        Ws[(idx & 127) * 132 + (idx >> 7)] = W[idx];
    }
    // gamma = x[3, node, 1]
    if (tid < NPB) {
        sgam[tid] = (tid < nn)
            ? x[((size_t)3 * N_NODES + base + tid) * HIDDEN + 1] : 0.f;
    }

    const float bias0 = b[o0];
    const float bias1 = b[o0 + 1];
    __syncthreads();

    for (int s = 0; s < 2; ++s) {
        // xs[h*130 + n] = x[s, base+n, h]  (in-bounds even past nn: reads
        // spill into the next s-slice of x; those lanes are discarded)
        const float* xsrc = x + ((size_t)s * N_NODES + base) * HIDDEN;
        for (int idx = tid; idx < NPB * HIDDEN; idx += 512) {
            const int n = idx >> 7, h = idx & 127;
            xs[h * 130 + n] = xsrc[idx];
        }
        __syncthreads();

        unsigned long long acc[2][8];
        #pragma unroll
        for (int oi = 0; oi < 2; ++oi)
            #pragma unroll
            for (int p = 0; p < 8; ++p) acc[oi][p] = 0ull;

        #pragma unroll 4
        for (int h = 0; h < HIDDEN; ++h) {
            const float2 wp = *reinterpret_cast<const float2*>(&Ws[h * 132 + o0]);
            const unsigned long long w20 = dup2(wp.x);
            const unsigned long long w21 = dup2(wp.y);
            const float* xr = &xs[h * 130 + n0];
            #pragma unroll
            for (int p = 0; p < 8; ++p) {
                const unsigned long long xv =
                    *reinterpret_cast<const unsigned long long*>(xr + 2 * p);
                acc[0][p] = ffma2(xv, w20, acc[0][p]);
                acc[1][p] = ffma2(xv, w21, acc[1][p]);
            }
        }

        // Epilogue: per node, store float2 over outputs (o0, o0+1).
        #pragma unroll
        for (int p = 0; p < 8; ++p) {
            float lo[2], hi[2];
            lo[0] = sigmoidf(__uint_as_float((unsigned)(acc[0][p] & 0xffffffffull)) + bias0);
            hi[0] = sigmoidf(__uint_as_float((unsigned)(acc[0][p] >> 32)) + bias0);
            lo[1] = sigmoidf(__uint_as_float((unsigned)(acc[1][p] & 0xffffffffull)) + bias1);
            hi[1] = sigmoidf(__uint_as_float((unsigned)(acc[1][p] >> 32)) + bias1);
            const int nA = n0 + 2 * p, nB = nA + 1;
            #pragma unroll
            for (int half = 0; half < 2; ++half) {
                const int n = half ? nB : nA;
                if (n >= nn) continue;
                const float v0 = half ? hi[0] : lo[0];
                const float v1 = half ? hi[1] : lo[1];
                const size_t off = ((size_t)(base + n)) * HIDDEN + o0;
                if (s == 0) {
                    *reinterpret_cast<float2*>(&g_S[off]) = make_float2(v0, v1);
                } else {
                    *reinterpret_cast<float2*>(&g_I[off]) = make_float2(v0, v1);
                    const float gm = sgam[n];
                    *reinterpret_cast<float2*>(&out[(size_t)2 * N_NODES * HIDDEN + off])
                        = make_float2(gm * v0, gm * v1);
                    *reinterpret_cast<float2*>(&out[(size_t)3 * N_NODES * HIDDEN + off])
                        = make_float2(0.f, 0.f);
                }
            }
        }
        __syncthreads();   // protect xs before next s overwrites it
    }
}

// ---------------------------------------------------------------------------
// K2: bin edges by destination row (indices are int32 per JAX default x64-off).
// ---------------------------------------------------------------------------
__global__ __launch_bounds__(256) void k_place(
    const int* __restrict__ rows, const int* __restrict__ cols, int n_edges)
{
    const int i = blockIdx.x * 256 + threadIdx.x;
    if (i >= n_edges) return;
    int r = rows[i], c = cols[i];
    r = min(max(r, 0), N_NODES - 1);
    c = min(max(c, 0), N_NODES - 1);
    const int slot = atomicAdd(&g_cnt[r], 1);
    if (slot < CAP) {
        g_bin[(size_t)r * CAP + slot] = c;
    } else {
        const int o = atomicAdd(&g_ovf_cnt, 1);
        g_ovf[2 * o] = r;
        g_ovf[2 * o + 1] = c;
    }
}

// ---------------------------------------------------------------------------
// K3: gather + finalize. Warp per node, MLP=8: AI = sum_{in-edges} I[col],
//     dS = -beta*AI*S ; dI = -dS - gamma*I. No float atomics.
// ---------------------------------------------------------------------------
__global__ __launch_bounds__(256) void k_gather_final(
    const float* __restrict__ x, float* __restrict__ out)
{
    const int node = (blockIdx.x * 256 + threadIdx.x) >> 5;
    if (node >= N_NODES) return;
    const int lane = threadIdx.x & 31;

    const int d = min(g_cnt[node], CAP);
    const int* __restrict__ bin = g_bin + (size_t)node * CAP;
    const float4* __restrict__ I4 = reinterpret_cast<const float4*>(g_I);

    float4 a = make_float4(0.f, 0.f, 0.f, 0.f);
    int i = 0;
    for (; i + 8 <= d; i += 8) {      // 8 outstanding 512B L2 loads per warp
        int c[8];
        #pragma unroll
        for (int k = 0; k < 8; ++k) c[k] = __ldg(&bin[i + k]);
        float4 v[8];
        #pragma unroll
        for (int k = 0; k < 8; ++k) v[k] = I4[(size_t)c[k] * 32 + lane];
        #pragma unroll
        for (int k = 0; k < 8; ++k) {
            a.x += v[k].x; a.y += v[k].y; a.z += v[k].z; a.w += v[k].w;
        }
    }
    if (i + 4 <= d) {
        int c[4];
        #pragma unroll
        for (int k = 0; k < 4; ++k) c[k] = __ldg(&bin[i + k]);
        float4 v[4];
        #pragma unroll
        for (int k = 0; k < 4; ++k) v[k] = I4[(size_t)c[k] * 32 + lane];
        #pragma unroll
        for (int k = 0; k < 4; ++k) {
            a.x += v[k].x; a.y += v[k].y; a.z += v[k].z; a.w += v[k].w;
        }
        i += 4;
    }
    for (; i < d; ++i) {
        const float4 v = I4[(size_t)__ldg(&bin[i]) * 32 + lane];
        a.x += v.x; a.y += v.y; a.z += v.z; a.w += v.w;
    }

    const float beta = x[((size_t)3 * N_NODES + node) * HIDDEN];
    const size_t fo = (size_t)node * 32 + lane;
    const float4 S4 = reinterpret_cast<const float4*>(g_S)[fo];
    const float4 G4 = reinterpret_cast<const float4*>(
        out + (size_t)2 * N_NODES * HIDDEN)[fo];

    float4 dS, dI;
    dS.x = -beta * a.x * S4.x;  dI.x = -dS.x - G4.x;
    dS.y = -beta * a.y * S4.y;  dI.y = -dS.y - G4.y;
    dS.z = -beta * a.z * S4.z;  dI.z = -dS.z - G4.z;
    dS.w = -beta * a.w * S4.w;  dI.w = -dS.w - G4.w;

    reinterpret_cast<float4*>(out)[fo] = dS;
    reinterpret_cast<float4*>(out + (size_t)N_NODES * HIDDEN)[fo] = dI;
}

// ---------------------------------------------------------------------------
// K4: overflow fix-up (expected empty) + re-zero counters for next call.
// ---------------------------------------------------------------------------
__global__ __launch_bounds__(256) void k_fix(
    const float* __restrict__ x, float* __restrict__ out)
{
    if (blockIdx.x == 0) {
        const int n = g_ovf_cnt;
        if (n > 0) {
            const long long total = (long long)n * HIDDEN;
            for (long long idx = threadIdx.x; idx < total; idx += 256) {
                const int e = (int)(idx >> 7);
                const int j = (int)(idx & 127);
                const int r = g_ovf[2 * e];
                const int c = g_ovf[2 * e + 1];
                const float v = g_I[(size_t)c * HIDDEN + j];
                const float beta = x[((size_t)3 * N_NODES + r) * HIDDEN];
                const float delta = -beta * v * g_S[(size_t)r * HIDDEN + j];
                atomicAdd(&out[(size_t)r * HIDDEN + j], delta);
                atomicAdd(&out[(size_t)N_NODES * HIDDEN + (size_t)r * HIDDEN + j], -delta);
            }
        }
        __syncthreads();
        if (threadIdx.x == 0) g_ovf_cnt = 0;
    }
    for (int i = blockIdx.x * 256 + threadIdx.x; i < N_NODES;
         i += gridDim.x * 256) {
        g_cnt[i] = 0;
    }
}

// ---------------------------------------------------------------------------
extern "C" void kernel_launch(void* const* d_in, const int* in_sizes, int n_in,
                              void* d_out, int out_size)
{
    const float* x    = (const float*)d_in[0];
    const float* W    = (const float*)d_in[1];
    const float* b    = (const float*)d_in[2];
    const int*   rows = (const int*)d_in[3];
    const int*   cols = (const int*)d_in[4];
    float*       out  = (float*)d_out;

    const int n_edges = in_sizes[3];

    const size_t smem = (size_t)(128 * 132 + 128 * 130 + 128) * sizeof(float);
    cudaFuncSetAttribute(k_gemm, cudaFuncAttributeMaxDynamicSharedMemorySize,
                         (int)smem);

    k_place<<<(n_edges + 255) / 256, 256>>>(rows, cols, n_edges);

    const int gemm_blocks = (N_NODES + NPB - 1) / NPB;
    k_gemm<<<gemm_blocks, 512, smem>>>(x, W, b, out);

    const int gf_blocks = (N_NODES * 32 + 255) / 256;  // warp per node
    k_gather_final<<<gf_blocks, 256>>>(x, out);

    k_fix<<<128, 256>>>(x, out);
}

// round 7
// speedup vs baseline: 2.4128x; 1.9052x over previous
#include <cuda_runtime.h>
#include <cstdint>

#define N_NODES 100000
#define HIDDEN  128
#define NPB     256   // nodes per CTA in GEMM kernel
#define CAP     48    // per-node edge bin capacity (Poisson mean 16; P(>=48)~1e-10)

// Scratch (device globals — allocation-free rule).
// INVARIANT: g_cnt[] and g_ovf_cnt are ZERO at kernel_launch entry
// (zero-init at module load; re-zeroed at the end of every call by k_fix).
__device__ __align__(16) float g_S  [(size_t)N_NODES * HIDDEN];
__device__ __align__(16) float g_I  [(size_t)N_NODES * HIDDEN];
__device__ int   g_cnt[N_NODES];
__device__ int   g_bin[(size_t)N_NODES * CAP];
__device__ int   g_ovf_cnt;
__device__ int   g_ovf[2 * 1600000];

__device__ __forceinline__ float sigmoidf(float v) {
    return 1.f / (1.f + __expf(-v));
}
__device__ __forceinline__ uint32_t to_tf32(float f) {
    uint32_t u;
    asm("cvt.rna.tf32.f32 %0, %1;" : "=r"(u) : "f"(f));
    return u;
}
__device__ __forceinline__ void mma_tf32(float* c, uint32_t a0, uint32_t a1,
                                         uint32_t a2, uint32_t a3,
                                         uint32_t b0, uint32_t b1) {
    asm volatile(
        "mma.sync.aligned.m16n8k8.row.col.f32.tf32.tf32.f32 "
        "{%0,%1,%2,%3}, {%4,%5,%6,%7}, {%8,%9}, {%0,%1,%2,%3};"
        : "+f"(c[0]), "+f"(c[1]), "+f"(c[2]), "+f"(c[3])
        : "r"(a0), "r"(a1), "r"(a2), "r"(a3), "r"(b0), "r"(b1));
}

// Shared layout (uint32 elements):
//   xs [256][132]  node-major tf32 x tile
//   Ws [128][132]  o-major tf32 W   (col-major B for mma: B[n][k])
//   sgam[256], sbias[128] as floats
#define XS_SZ   (256 * 132)
#define WS_SZ   (128 * 132)
#define SM_U32  (XS_SZ + WS_SZ + 256 + 128)

// ---------------------------------------------------------------------------
// K1: tf32 mma.sync sigmoid-GEMM. 512 threads = 16 warps; warp w computes
// nodes [w*16, w*16+16) x all 128 outputs, K=128 in 16 k-steps.
// Fuses: g_S, g_I, out[2] = gamma*I, out[3] = 0.
// ---------------------------------------------------------------------------
__global__ __launch_bounds__(512, 1) void k_gemm(
    const float* __restrict__ x, const float* __restrict__ W,
    const float* __restrict__ b, float* __restrict__ out)
{
    extern __shared__ uint32_t sh[];
    uint32_t* xs    = sh;
    uint32_t* Ws    = sh + XS_SZ;
    float*    sgam  = reinterpret_cast<float*>(sh + XS_SZ + WS_SZ);
    float*    sbias = sgam + 256;

    const int tid  = threadIdx.x;
    const int warp = tid >> 5;
    const int lane = tid & 31;
    const int grp  = lane >> 2;   // 0..7
    const int qk   = lane & 3;    // 0..3
    const int base = blockIdx.x * NPB;
    const int nn   = min(NPB, N_NODES - base);
    const int m0   = warp * 16;

    // Ws[o*132 + h] = tf32(W[o*128 + h])   (B col-major: B[n][k])
    for (int idx = tid; idx < HIDDEN * HIDDEN; idx += 512) {
        Ws[(idx >> 7) * 132 + (idx & 127)] = to_tf32(W[idx]);
    }
    if (tid < HIDDEN) sbias[tid] = b[tid];
    // gamma = x[3, node, 1]
    for (int n = tid; n < NPB; n += 512) {
        sgam[n] = (n < nn)
            ? x[((size_t)3 * N_NODES + base + n) * HIDDEN + 1] : 0.f;
    }

    for (int s = 0; s < 2; ++s) {
        // xs[n*132 + h] = tf32(x[s, base+n, h]); rows >= nn read into the
        // next s-slice (in-bounds of x, results discarded).
        const float* xsrc = x + ((size_t)s * N_NODES + base) * HIDDEN;
        __syncthreads();   // previous-iter consumers done before overwrite
        for (int idx = tid; idx < NPB * HIDDEN; idx += 512) {
            xs[(idx >> 7) * 132 + (idx & 127)] = to_tf32(xsrc[idx]);
        }
        __syncthreads();

        float acc[16][4];
        #pragma unroll
        for (int nb = 0; nb < 16; ++nb)
            #pragma unroll
            for (int i = 0; i < 4; ++i) acc[nb][i] = 0.f;

        const uint32_t* xrow0 = xs + (m0 + grp) * 132;       // rows m0+grp
        const uint32_t* xrow1 = xrow0 + 8 * 132;             // rows m0+grp+8

        #pragma unroll 2
        for (int k0 = 0; k0 < 16; ++k0) {
            const int kb = k0 * 8;
            const uint32_t a0 = xrow0[kb + qk];
            const uint32_t a1 = xrow1[kb + qk];
            const uint32_t a2 = xrow0[kb + qk + 4];
            const uint32_t a3 = xrow1[kb + qk + 4];
            #pragma unroll
            for (int nb = 0; nb < 16; ++nb) {
                const uint32_t* wrow = Ws + (nb * 8 + grp) * 132 + kb;
                mma_tf32(acc[nb], a0, a1, a2, a3, wrow[qk], wrow[qk + 4]);
            }
        }

        // Epilogue: thread owns rows r0 = m0+grp, r1 = r0+8;
        // per nb, cols nb*8 + 2*qk (+1): float2 stores, 32B-sector coalesced.
        const int r0 = m0 + grp, r1 = r0 + 8;
        const float gm0 = sgam[r0], gm1 = sgam[r1];
        #pragma unroll
        for (int nb = 0; nb < 16; ++nb) {
            const int col = nb * 8 + 2 * qk;
            const float b0 = sbias[col], b1 = sbias[col + 1];
            const float v00 = sigmoidf(acc[nb][0] + b0);
            const float v01 = sigmoidf(acc[nb][1] + b1);
            const float v10 = sigmoidf(acc[nb][2] + b0);
            const float v11 = sigmoidf(acc[nb][3] + b1);
            const size_t o0 = ((size_t)(base + r0)) * HIDDEN + col;
            const size_t o1 = ((size_t)(base + r1)) * HIDDEN + col;
            if (s == 0) {
                if (r0 < nn) *reinterpret_cast<float2*>(&g_S[o0]) = make_float2(v00, v01);
                if (r1 < nn) *reinterpret_cast<float2*>(&g_S[o1]) = make_float2(v10, v11);
            } else {
                if (r0 < nn) {
                    *reinterpret_cast<float2*>(&g_I[o0]) = make_float2(v00, v01);
                    *reinterpret_cast<float2*>(&out[(size_t)2 * N_NODES * HIDDEN + o0])
                        = make_float2(gm0 * v00, gm0 * v01);
                    *reinterpret_cast<float2*>(&out[(size_t)3 * N_NODES * HIDDEN + o0])
                        = make_float2(0.f, 0.f);
                }
                if (r1 < nn) {
                    *reinterpret_cast<float2*>(&g_I[o1]) = make_float2(v10, v11);
                    *reinterpret_cast<float2*>(&out[(size_t)2 * N_NODES * HIDDEN + o1])
                        = make_float2(gm1 * v10, gm1 * v11);
                    *reinterpret_cast<float2*>(&out[(size_t)3 * N_NODES * HIDDEN + o1])
                        = make_float2(0.f, 0.f);
                }
            }
        }
    }
}

// ---------------------------------------------------------------------------
// K2: bin edges by destination row (indices are int32 per JAX default x64-off).
// ---------------------------------------------------------------------------
__global__ __launch_bounds__(256) void k_place(
    const int* __restrict__ rows, const int* __restrict__ cols, int n_edges)
{
    const int i = blockIdx.x * 256 + threadIdx.x;
    if (i >= n_edges) return;
    int r = rows[i], c = cols[i];
    r = min(max(r, 0), N_NODES - 1);
    c = min(max(c, 0), N_NODES - 1);
    const int slot = atomicAdd(&g_cnt[r], 1);
    if (slot < CAP) {
        g_bin[(size_t)r * CAP + slot] = c;
    } else {
        const int o = atomicAdd(&g_ovf_cnt, 1);
        g_ovf[2 * o] = r;
        g_ovf[2 * o + 1] = c;
    }
}

// ---------------------------------------------------------------------------
// K3: gather + finalize. Warp per node, MLP=8: AI = sum_{in-edges} I[col],
//     dS = -beta*AI*S ; dI = -dS - gamma*I. No float atomics.
// ---------------------------------------------------------------------------
__global__ __launch_bounds__(256) void k_gather_final(
    const float* __restrict__ x, float* __restrict__ out)
{
    const int node = (blockIdx.x * 256 + threadIdx.x) >> 5;
    if (node >= N_NODES) return;
    const int lane = threadIdx.x & 31;

    const int d = min(g_cnt[node], CAP);
    const int* __restrict__ bin = g_bin + (size_t)node * CAP;
    const float4* __restrict__ I4 = reinterpret_cast<const float4*>(g_I);

    float4 a = make_float4(0.f, 0.f, 0.f, 0.f);
    int i = 0;
    for (; i + 8 <= d; i += 8) {      // 8 outstanding 512B L2 loads per warp
        int c[8];
        #pragma unroll
        for (int k = 0; k < 8; ++k) c[k] = __ldg(&bin[i + k]);
        float4 v[8];
        #pragma unroll
        for (int k = 0; k < 8; ++k) v[k] = I4[(size_t)c[k] * 32 + lane];
        #pragma unroll
        for (int k = 0; k < 8; ++k) {
            a.x += v[k].x; a.y += v[k].y; a.z += v[k].z; a.w += v[k].w;
        }
    }
    if (i + 4 <= d) {
        int c[4];
        #pragma unroll
        for (int k = 0; k < 4; ++k) c[k] = __ldg(&bin[i + k]);
        float4 v[4];
        #pragma unroll
        for (int k = 0; k < 4; ++k) v[k] = I4[(size_t)c[k] * 32 + lane];
        #pragma unroll
        for (int k = 0; k < 4; ++k) {
            a.x += v[k].x; a.y += v[k].y; a.z += v[k].z; a.w += v[k].w;
        }
        i += 4;
    }
    for (; i < d; ++i) {
        const float4 v = I4[(size_t)__ldg(&bin[i]) * 32 + lane];
        a.x += v.x; a.y += v.y; a.z += v.z; a.w += v.w;
    }

    const float beta = x[((size_t)3 * N_NODES + node) * HIDDEN];
    const size_t fo = (size_t)node * 32 + lane;
    const float4 S4 = reinterpret_cast<const float4*>(g_S)[fo];
    const float4 G4 = reinterpret_cast<const float4*>(
        out + (size_t)2 * N_NODES * HIDDEN)[fo];

    float4 dS, dI;
    dS.x = -beta * a.x * S4.x;  dI.x = -dS.x - G4.x;
    dS.y = -beta * a.y * S4.y;  dI.y = -dS.y - G4.y;
    dS.z = -beta * a.z * S4.z;  dI.z = -dS.z - G4.z;
    dS.w = -beta * a.w * S4.w;  dI.w = -dS.w - G4.w;

    reinterpret_cast<float4*>(out)[fo] = dS;
    reinterpret_cast<float4*>(out + (size_t)N_NODES * HIDDEN)[fo] = dI;
}

// ---------------------------------------------------------------------------
// K4: overflow fix-up (expected empty) + re-zero counters for next call.
// ---------------------------------------------------------------------------
__global__ __launch_bounds__(256) void k_fix(
    const float* __restrict__ x, float* __restrict__ out)
{
    if (blockIdx.x == 0) {
        const int n = g_ovf_cnt;
        if (n > 0) {
            const long long total = (long long)n * HIDDEN;
            for (long long idx = threadIdx.x; idx < total; idx += 256) {
                const int e = (int)(idx >> 7);
                const int j = (int)(idx & 127);
                const int r = g_ovf[2 * e];
                const int c = g_ovf[2 * e + 1];
                const float v = g_I[(size_t)c * HIDDEN + j];
                const float beta = x[((size_t)3 * N_NODES + r) * HIDDEN];
                const float delta = -beta * v * g_S[(size_t)r * HIDDEN + j];
                atomicAdd(&out[(size_t)r * HIDDEN + j], delta);
                atomicAdd(&out[(size_t)N_NODES * HIDDEN + (size_t)r * HIDDEN + j], -delta);
            }
        }
        __syncthreads();
        if (threadIdx.x == 0) g_ovf_cnt = 0;
    }
    for (int i = blockIdx.x * 256 + threadIdx.x; i < N_NODES;
         i += gridDim.x * 256) {
        g_cnt[i] = 0;
    }
}

// ---------------------------------------------------------------------------
extern "C" void kernel_launch(void* const* d_in, const int* in_sizes, int n_in,
                              void* d_out, int out_size)
{
    const float* x    = (const float*)d_in[0];
    const float* W    = (const float*)d_in[1];
    const float* b    = (const float*)d_in[2];
    const int*   rows = (const int*)d_in[3];
    const int*   cols = (const int*)d_in[4];
    float*       out  = (float*)d_out;

    const int n_edges = in_sizes[3];

    const size_t smem = (size_t)SM_U32 * sizeof(uint32_t);
    cudaFuncSetAttribute(k_gemm, cudaFuncAttributeMaxDynamicSharedMemorySize,
                         (int)smem);

    k_place<<<(n_edges + 255) / 256, 256>>>(rows, cols, n_edges);

    const int gemm_blocks = (N_NODES + NPB - 1) / NPB;
    k_gemm<<<gemm_blocks, 512, smem>>>(x, W, b, out);

    const int gf_blocks = (N_NODES * 32 + 255) / 256;  // warp per node
    k_gather_final<<<gf_blocks, 256>>>(x, out);

    k_fix<<<128, 256>>>(x, out);
}